// round 16
// baseline (speedup 1.0000x reference)
#include <cuda_runtime.h>
#include <cuda_fp16.h>
#include <math_constants.h>
#include <cstdint>

// Problem constants (fixed by the dataset)
#define NN   50000
#define EE   600000
#define GG   1000
#define HID  128
#define INF_ 64
#define EPS  1e-5f
#define SLOPE 0.01f

#define NB_SCAN ((NN + 255) / 256)    // 196
#define BUF_E 8                       // edges per TMA batch per warp
#define GEMM_GRID ((NN + 127) / 128)  // 391 (128-row blocks)

// ---------------------------------------------------------------------------
// Scratch (static __device__ arrays; zero-initialized at load; the trailing
// k_setup_zero restores zeros for the NEXT call -> identical state per call).
// ---------------------------------------------------------------------------
__device__ __align__(256) __half g_hs [NN * HID];  // (x@W)*cs fp16, 256B rows
__device__ float  g_y  [NN * HID];
__device__ float  g_cs [NN];
__device__ float  g_cd [NN];
__device__ int    g_deg[2 * NN];     // [0,N): outdeg, [N,2N): indeg
__device__ int    g_csr_start[NN];   // segment base per node (non-monotonic)
__device__ int    g_cursor[NN];
__device__ int    g_csr_src[EE];
__device__ int    g_total[1];        // atomic segment allocator
__device__ float  g_stats[3 * 2 * HID];
__device__ int    g_gstart[GG + 1];

__device__ __forceinline__ float leaky(float v) { return v > 0.f ? v : SLOPE * v; }

__device__ __forceinline__ void alpha_beta(const float* __restrict__ stats,
                                           const float* __restrict__ gw,
                                           const float* __restrict__ gb,
                                           const float* __restrict__ gs,
                                           int c, float& a, float& b) {
    float m   = stats[c] * (1.f / (float)NN);
    float ex2 = stats[HID + c] * (1.f / (float)NN);
    float s   = gs[c];
    float var = ex2 - m * m * (2.f * s - s * s);
    float inv = rsqrtf(var + EPS);
    a = inv * gw[c];
    b = gb[c] - s * m * a;
}

// packed f32x2 helpers
__device__ __forceinline__ unsigned long long pack2(float x, float y) {
    unsigned long long r;
    asm("mov.b64 %0, {%1, %2};" : "=l"(r) : "f"(x), "f"(y));
    return r;
}
__device__ __forceinline__ void unpack2(unsigned long long p, float& x, float& y) {
    asm("mov.b64 {%0, %1}, %2;" : "=f"(x), "=f"(y) : "l"(p));
}
__device__ __forceinline__ void fma2(unsigned long long& d, unsigned long long a,
                                     unsigned long long b) {
    asm("fma.rn.f32x2 %0, %1, %2, %0;" : "+l"(d) : "l"(a), "l"(b));
}

__device__ __forceinline__ uint32_t smem_u32(const void* p) {
    return (uint32_t)__cvta_generic_to_shared(p);
}
__device__ __forceinline__ void mbar_wait(uint32_t mbar, uint32_t parity) {
    asm volatile(
        "{\n\t.reg .pred P1;\n\t"
        "W_%=:\n\t"
        "mbarrier.try_wait.parity.acquire.cta.shared::cta.b64 P1, [%0], %1, 0x989680;\n\t"
        "@P1 bra.uni D_%=;\n\t"
        "bra.uni W_%=;\n\t"
        "D_%=:\n\t}"
        :: "r"(mbar), "r"(parity) : "memory");
}

// ---------------------------------------------------------------------------
// Trailing zero: restores deg + stats + total to zero for the NEXT call.
// Runs after the final readout (nothing later reads these this call).
// ---------------------------------------------------------------------------
__global__ void k_setup_zero(int* __restrict__ deg, float* __restrict__ stats,
                             int* __restrict__ total) {
    int i = blockIdx.x * blockDim.x + threadIdx.x;
    int stride = gridDim.x * blockDim.x;
    for (int j = i; j < 2 * NN; j += stride) deg[j] = 0;
    for (int j = i; j < 3 * 2 * HID; j += stride) stats[j] = 0.f;
    if (i == 0) total[0] = 0;
}

// ---------------------------------------------------------------------------
// Degrees: 4 edges/thread; deg[] arrives zeroed (trailing zero / load init)
// ---------------------------------------------------------------------------
__global__ void k_degrees(const int* __restrict__ src, const int* __restrict__ dst,
                          int* __restrict__ deg) {
    int base = (blockIdx.x * blockDim.x + threadIdx.x) * 4;
    if (base >= EE) return;
    int4 s4 = *(const int4*)&src[base];
    int4 d4 = *(const int4*)&dst[base];
    atomicAdd(&deg[s4.x], 1);
    atomicAdd(&deg[s4.y], 1);
    atomicAdd(&deg[s4.z], 1);
    atomicAdd(&deg[s4.w], 1);
    atomicAdd(&deg[NN + d4.x], 1);
    atomicAdd(&deg[NN + d4.y], 1);
    atomicAdd(&deg[NN + d4.z], 1);
    atomicAdd(&deg[NN + d4.w], 1);
}

// ---------------------------------------------------------------------------
// Fused post-degree setup: invdeg + gstart + CSR segment assignment via
// block-local scan + one global atomicAdd (segment order irrelevant).
// ---------------------------------------------------------------------------
__global__ void k_misc(const int* __restrict__ deg, const int* __restrict__ gid,
                       float* __restrict__ cs, float* __restrict__ cd,
                       int* __restrict__ gstart, int* __restrict__ csr_start,
                       int* __restrict__ cursor, int* __restrict__ total) {
    __shared__ int sh[256];
    __shared__ int s_base;
    int t = threadIdx.x;
    int i = blockIdx.x * 256 + t;
    int v = 0;
    if (i < NN) {
        int od = deg[i], id = deg[NN + i];
        cs[i] = rsqrtf(fmaxf((float)od, 1.f));
        cd[i] = rsqrtf(fmaxf((float)id, 1.f));
        v = id;
        int g  = gid[i];
        int gp = (i == 0) ? -1 : gid[i - 1];
        for (int gg = gp + 1; gg <= g; gg++) gstart[gg] = i;
        if (i == NN - 1)
            for (int gg = g + 1; gg <= GG; gg++) gstart[gg] = NN;
    }
    sh[t] = v;
    __syncthreads();
    for (int o = 1; o < 256; o <<= 1) {
        int tv = (t >= o) ? sh[t - o] : 0;
        __syncthreads();
        sh[t] += tv;
        __syncthreads();
    }
    if (t == 255) s_base = atomicAdd(total, sh[255]);
    __syncthreads();
    if (i < NN) {
        int start = s_base + sh[t] - v;
        csr_start[i] = start;
        cursor[i] = start;
    }
}

// ---------------------------------------------------------------------------
// CSR fill: 4 edges per thread
// ---------------------------------------------------------------------------
__global__ void k_fill_csr(const int* __restrict__ src, const int* __restrict__ dst,
                           int* __restrict__ cursor, int* __restrict__ csr_src) {
    int base = (blockIdx.x * blockDim.x + threadIdx.x) * 4;
    if (base >= EE) return;
    int4 s4 = *(const int4*)&src[base];
    int4 d4 = *(const int4*)&dst[base];
    int p0 = atomicAdd(&cursor[d4.x], 1);
    int p1 = atomicAdd(&cursor[d4.y], 1);
    int p2 = atomicAdd(&cursor[d4.z], 1);
    int p3 = atomicAdd(&cursor[d4.w], 1);
    csr_src[p0] = s4.x;
    csr_src[p1] = s4.y;
    csr_src[p2] = s4.z;
    csr_src[p3] = s4.w;
}

// ---------------------------------------------------------------------------
// GEMM device body (packed f32x2): block = 128 rows x 128 cols, 8 warps,
// micro-tile 16 rows x 4 cols per thread (8 packed row-pairs).
// ---------------------------------------------------------------------------
template <int K, bool NORM>
__device__ __forceinline__ void gemm_body(
    int blk, const float* __restrict__ X, const float* __restrict__ W,
    const float* __restrict__ cs, const float* __restrict__ s_a,
    const float* __restrict__ s_b, __half* __restrict__ out,
    float (*Ws)[HID], float (*Xs)[132]) {
    int tid = threadIdx.x;
    int tx = tid & 31, ty = tid >> 5;
    int row0 = blk * 128;
    int rb = ty * 16, cb = tx * 4;

    unsigned long long acc[8][4];
#pragma unroll
    for (int i = 0; i < 8; i++)
#pragma unroll
        for (int j = 0; j < 4; j++) acc[i][j] = 0ull;

    for (int k0 = 0; k0 < K; k0 += 32) {
        for (int i = tid; i < 32 * 32; i += 256) {
            int k = i >> 5, c = (i & 31) * 4;
            *(float4*)&Ws[k][c] = *(const float4*)&W[(k0 + k) * HID + c];
        }
        for (int i = tid; i < 128 * 8; i += 256) {
            int r = i >> 3, kq = (i & 7) * 4;
            int g = row0 + r;
            float4 v = make_float4(0.f, 0.f, 0.f, 0.f);
            if (g < NN) v = *(const float4*)&X[(size_t)g * K + k0 + kq];
            if (NORM) {
                float4 a = *(const float4*)&s_a[k0 + kq];
                float4 b = *(const float4*)&s_b[k0 + kq];
                v.x = leaky(v.x * a.x + b.x);
                v.y = leaky(v.y * a.y + b.y);
                v.z = leaky(v.z * a.z + b.z);
                v.w = leaky(v.w * a.w + b.w);
            }
            Xs[kq + 0][r] = v.x;
            Xs[kq + 1][r] = v.y;
            Xs[kq + 2][r] = v.z;
            Xs[kq + 3][r] = v.w;
        }
        __syncthreads();

#pragma unroll
        for (int k = 0; k < 32; k++) {
            ulonglong2 x0 = *(const ulonglong2*)&Xs[k][rb];
            ulonglong2 x1 = *(const ulonglong2*)&Xs[k][rb + 4];
            ulonglong2 x2 = *(const ulonglong2*)&Xs[k][rb + 8];
            ulonglong2 x3 = *(const ulonglong2*)&Xs[k][rb + 12];
            float4 w = *(const float4*)&Ws[k][cb];
            unsigned long long w0 = pack2(w.x, w.x);
            unsigned long long w1 = pack2(w.y, w.y);
            unsigned long long w2 = pack2(w.z, w.z);
            unsigned long long w3 = pack2(w.w, w.w);
            fma2(acc[0][0], x0.x, w0); fma2(acc[0][1], x0.x, w1);
            fma2(acc[0][2], x0.x, w2); fma2(acc[0][3], x0.x, w3);
            fma2(acc[1][0], x0.y, w0); fma2(acc[1][1], x0.y, w1);
            fma2(acc[1][2], x0.y, w2); fma2(acc[1][3], x0.y, w3);
            fma2(acc[2][0], x1.x, w0); fma2(acc[2][1], x1.x, w1);
            fma2(acc[2][2], x1.x, w2); fma2(acc[2][3], x1.x, w3);
            fma2(acc[3][0], x1.y, w0); fma2(acc[3][1], x1.y, w1);
            fma2(acc[3][2], x1.y, w2); fma2(acc[3][3], x1.y, w3);
            fma2(acc[4][0], x2.x, w0); fma2(acc[4][1], x2.x, w1);
            fma2(acc[4][2], x2.x, w2); fma2(acc[4][3], x2.x, w3);
            fma2(acc[5][0], x2.y, w0); fma2(acc[5][1], x2.y, w1);
            fma2(acc[5][2], x2.y, w2); fma2(acc[5][3], x2.y, w3);
            fma2(acc[6][0], x3.x, w0); fma2(acc[6][1], x3.x, w1);
            fma2(acc[6][2], x3.x, w2); fma2(acc[6][3], x3.x, w3);
            fma2(acc[7][0], x3.y, w0); fma2(acc[7][1], x3.y, w1);
            fma2(acc[7][2], x3.y, w2); fma2(acc[7][3], x3.y, w3);
        }
        __syncthreads();
    }

#pragma unroll
    for (int rp = 0; rp < 8; rp++) {
        float lo[4], hi[4];
#pragma unroll
        for (int c = 0; c < 4; c++) unpack2(acc[rp][c], lo[c], hi[c]);
        int g0 = row0 + rb + 2 * rp;
        int g1 = g0 + 1;
        if (g0 < NN) {
            float c0 = __ldg(&cs[g0]);
            __half2 p0 = __floats2half2_rn(lo[0] * c0, lo[1] * c0);
            __half2 p1 = __floats2half2_rn(lo[2] * c0, lo[3] * c0);
            uint2 u;
            u.x = *reinterpret_cast<uint32_t*>(&p0);
            u.y = *reinterpret_cast<uint32_t*>(&p1);
            *(uint2*)&out[(size_t)g0 * HID + cb] = u;
        }
        if (g1 < NN) {
            float c1 = __ldg(&cs[g1]);
            __half2 p0 = __floats2half2_rn(hi[0] * c1, hi[1] * c1);
            __half2 p1 = __floats2half2_rn(hi[2] * c1, hi[3] * c1);
            uint2 u;
            u.x = *reinterpret_cast<uint32_t*>(&p0);
            u.y = *reinterpret_cast<uint32_t*>(&p1);
            *(uint2*)&out[(size_t)g1 * HID + cb] = u;
        }
    }
}

// ---------------------------------------------------------------------------
// Readout device body: one graph, 256 threads = 128 channels x 2 phases.
// ---------------------------------------------------------------------------
__device__ __forceinline__ void readout_body(
    int g, const float* __restrict__ y, float a, float b,
    const int* __restrict__ gstart, float* __restrict__ out, int layer,
    float* s_r0, float* s_r1, float* s_r2) {
    int t = threadIdx.x;
    int c = t & 127, ph = t >> 7;
    int s0 = gstart[g], s1 = gstart[g + 1];
    float sum = 0.f, mx = -CUDART_INF_F, mn = CUDART_INF_F;
    for (int r = s0 + ph; r < s1; r += 2) {
        float v = leaky(__ldg(&y[(size_t)r * HID + c]) * a + b);
        sum += v;
        mx = fmaxf(mx, v);
        mn = fminf(mn, v);
    }
    s_r0[t] = sum; s_r1[t] = mx; s_r2[t] = mn;
    __syncthreads();
    if (ph == 0) {
        sum += s_r0[t + 128];
        mx = fmaxf(mx, s_r1[t + 128]);
        mn = fminf(mn, s_r2[t + 128]);
        int cnt = s1 - s0;
        float mean = sum / fmaxf((float)cnt, 1.f);
        if (cnt == 0) { mx = 0.f; mn = 0.f; }
        float* o = out + (size_t)g * (9 * HID) + layer * (3 * HID);
        o[c]           = leaky(mean);
        o[HID + c]     = leaky(mx);
        o[2 * HID + c] = leaky(mn);
    }
}

// ---------------------------------------------------------------------------
// Layer-0 GEMM (no norm). Launched at slot #4 -> profiled by ncu.
// ---------------------------------------------------------------------------
__global__ void __launch_bounds__(256, 2)
k_gemm0(const float* __restrict__ X, const float* __restrict__ W,
        const float* __restrict__ cs, __half* __restrict__ out) {
    __shared__ float Ws[32][HID];
    __shared__ float Xs[32][132];
    gemm_body<INF_, false>(blockIdx.x, X, W, cs, nullptr, nullptr, out, Ws, Xs);
}

// ---------------------------------------------------------------------------
// Combined: blocks [0,GEMM_GRID) gemm(L) w/ norm(L-1); [GEMM_GRID,+GG)
// readout(L-1). Both depend only on agg(L-1); disjoint memory.
// ---------------------------------------------------------------------------
__global__ void __launch_bounds__(256, 2)
k_gemm_ro(const float* __restrict__ y, const float* __restrict__ W,
          const float* __restrict__ cs,
          const float* __restrict__ stats, const float* __restrict__ gw,
          const float* __restrict__ gb, const float* __restrict__ gs,
          __half* __restrict__ hs, const int* __restrict__ gstart,
          float* __restrict__ out, int prev_layer) {
    __shared__ float Ws[32][HID];
    __shared__ float Xs[32][132];
    __shared__ float s_a[HID], s_b[HID];

    int bid = blockIdx.x;
    if (bid < GEMM_GRID) {
        if (threadIdx.x < HID) {
            float a, b;
            alpha_beta(stats, gw, gb, gs, threadIdx.x, a, b);
            s_a[threadIdx.x] = a;
            s_b[threadIdx.x] = b;
        }
        __syncthreads();
        gemm_body<HID, true>(bid, y, W, cs, s_a, s_b, hs, Ws, Xs);
    } else {
        float a, b;
        alpha_beta(stats, gw, gb, gs, threadIdx.x & 127, a, b);
        float* s_r0 = &Ws[0][0];
        float* s_r1 = &Ws[2][0];
        float* s_r2 = &Ws[4][0];
        readout_body(bid - GEMM_GRID, y, a, b, gstart, out, prev_layer,
                     s_r0, s_r1, s_r2);
    }
}

// ---------------------------------------------------------------------------
// Standalone readout (final layer)
// ---------------------------------------------------------------------------
__global__ void __launch_bounds__(256)
k_readout(const float* __restrict__ y, const float* __restrict__ stats,
          const float* __restrict__ gw, const float* __restrict__ gb,
          const float* __restrict__ gs, const int* __restrict__ gstart,
          float* __restrict__ out, int layer) {
    __shared__ float s_r0[256], s_r1[256], s_r2[256];
    float a, b;
    alpha_beta(stats, gw, gb, gs, threadIdx.x & 127, a, b);
    readout_body(blockIdx.x, y, a, b, gstart, out, layer, s_r0, s_r1, s_r2);
}

// ---------------------------------------------------------------------------
// TMA-bulk aggregation (round-11 proven). end = start + indeg[d].
// ---------------------------------------------------------------------------
__global__ void __launch_bounds__(256)
k_aggstats(const __half* __restrict__ hs, const int* __restrict__ csr_start,
           const int* __restrict__ indeg, const int* __restrict__ csr_src,
           const float* __restrict__ cd,
           float* __restrict__ y, float* __restrict__ stats) {
    __shared__ __align__(16) char buf[8][BUF_E * 256];   // 16 KB
    __shared__ __align__(8) uint64_t mbar[8];
    __shared__ float s_sum[8][HID];
    __shared__ float s_sq [8][HID];

    int warp = threadIdx.x >> 5, lane = threadIdx.x & 31;
    int lg = lane >> 4, li = lane & 15;
    int d = blockIdx.x * 8 + warp;
    uint32_t mb = smem_u32(&mbar[warp]);

    if (lane == 0)
        asm volatile("mbarrier.init.shared.b64 [%0], 1;" :: "r"(mb) : "memory");
    __syncwarp();

    float2 acc[4];
#pragma unroll
    for (int j = 0; j < 4; j++) acc[j] = make_float2(0.f, 0.f);

    if (d < NN) {
        int start = __ldg(&csr_start[d]);
        int end   = start + __ldg(&indeg[d]);
        uint32_t parity = 0;
        for (int i = start; i < end; i += BUF_E) {
            int cnt = min(BUF_E, end - i);
            if (lane == 0)
                asm volatile(
                    "mbarrier.arrive.expect_tx.shared.b64 _, [%0], %1;"
                    :: "r"(mb), "r"((uint32_t)(cnt * 256)) : "memory");
            __syncwarp();
            if (lane < cnt) {
                int s = __ldg(&csr_src[i + lane]);
                uint32_t dstp = smem_u32(&buf[warp][lane * 256]);
                const void* gsrc = hs + (size_t)s * HID;
                asm volatile(
                    "cp.async.bulk.shared::cluster.global.mbarrier::complete_tx::bytes "
                    "[%0], [%1], %2, [%3];"
                    :: "r"(dstp), "l"(gsrc), "r"(256u), "r"(mb) : "memory");
            }
            mbar_wait(mb, parity);
            parity ^= 1u;
            for (int j = lg; j < cnt; j += 2) {
                uint4 u = *(const uint4*)&buf[warp][j * 256 + li * 16];
                float2 f;
                f = __half22float2(*reinterpret_cast<__half2*>(&u.x));
                acc[0].x += f.x; acc[0].y += f.y;
                f = __half22float2(*reinterpret_cast<__half2*>(&u.y));
                acc[1].x += f.x; acc[1].y += f.y;
                f = __half22float2(*reinterpret_cast<__half2*>(&u.z));
                acc[2].x += f.x; acc[2].y += f.y;
                f = __half22float2(*reinterpret_cast<__half2*>(&u.w));
                acc[3].x += f.x; acc[3].y += f.y;
            }
            __syncwarp();
        }
#pragma unroll
        for (int j = 0; j < 4; j++) {
            acc[j].x += __shfl_xor_sync(0xffffffffu, acc[j].x, 16);
            acc[j].y += __shfl_xor_sync(0xffffffffu, acc[j].y, 16);
        }
        float c = __ldg(&cd[d]);
#pragma unroll
        for (int j = 0; j < 4; j++) { acc[j].x *= c; acc[j].y *= c; }
        if (lg == 0) {
            float4 o0 = make_float4(acc[0].x, acc[0].y, acc[1].x, acc[1].y);
            float4 o1 = make_float4(acc[2].x, acc[2].y, acc[3].x, acc[3].y);
            *(float4*)(y + (size_t)d * HID + li * 8)     = o0;
            *(float4*)(y + (size_t)d * HID + li * 8 + 4) = o1;
        }
    }

    if (lg == 0) {
#pragma unroll
        for (int j = 0; j < 4; j++) {
            int c0 = li * 8 + 2 * j;
            float vx = (d < NN) ? acc[j].x : 0.f;
            float vy = (d < NN) ? acc[j].y : 0.f;
            s_sum[warp][c0]     = vx;
            s_sum[warp][c0 + 1] = vy;
            s_sq [warp][c0]     = vx * vx;
            s_sq [warp][c0 + 1] = vy * vy;
        }
    }
    __syncthreads();

    int t = threadIdx.x;
    if (t < HID) {
        float s = 0.f;
#pragma unroll
        for (int w = 0; w < 8; w++) s += s_sum[w][t];
        atomicAdd(&stats[t], s);
    } else {
        int c = t - HID;
        float s = 0.f;
#pragma unroll
        for (int w = 0; w < 8; w++) s += s_sq[w][c];
        atomicAdd(&stats[HID + c], s);
    }
}

// ---------------------------------------------------------------------------
// Launch: single stream, 11 launches. gemm0 at slot #4 (profiled);
// trailing k_setup_zero restores zeroed state for the next call.
// ---------------------------------------------------------------------------
extern "C" void kernel_launch(void* const* d_in, const int* in_sizes, int n_in,
                              void* d_out, int out_size) {
    const float* X   = (const float*)d_in[0];
    const float* W1  = (const float*)d_in[1];
    const float* W2  = (const float*)d_in[2];
    const float* W3  = (const float*)d_in[3];
    const float* gw  = (const float*)d_in[4];
    const float* gb  = (const float*)d_in[5];
    const float* gs  = (const float*)d_in[6];
    const int*   src = (const int*)d_in[7];
    const int*   dst = (const int*)d_in[8];
    const int*   gid = (const int*)d_in[9];
    float* out = (float*)d_out;

    __half* hs;
    float *y, *cs, *cd, *stats;
    int *deg, *gstart, *csr_start, *cursor, *csr_src, *total;
    cudaGetSymbolAddress((void**)&hs,        g_hs);
    cudaGetSymbolAddress((void**)&y,         g_y);
    cudaGetSymbolAddress((void**)&cs,        g_cs);
    cudaGetSymbolAddress((void**)&cd,        g_cd);
    cudaGetSymbolAddress((void**)&stats,     g_stats);
    cudaGetSymbolAddress((void**)&deg,       g_deg);
    cudaGetSymbolAddress((void**)&gstart,    g_gstart);
    cudaGetSymbolAddress((void**)&csr_start, g_csr_start);
    cudaGetSymbolAddress((void**)&cursor,    g_cursor);
    cudaGetSymbolAddress((void**)&csr_src,   g_csr_src);
    cudaGetSymbolAddress((void**)&total,     g_total);

    const int agg_grid   = (NN + 7) / 8;
    const int edge4_grid = (EE / 4 + 255) / 256;
    int* indeg = deg + NN;

    // --- setup: 3 launches (deg/stats/total arrive zeroed) ---
    k_degrees<<<edge4_grid, 256>>>(src, dst, deg);
    k_misc<<<NB_SCAN, 256>>>(deg, gid, cs, cd, gstart, csr_start, cursor, total);
    k_fill_csr<<<edge4_grid, 256>>>(src, dst, cursor, csr_src);

    // --- layer 0 (gemm0 at launch slot #4 -> gets profiled) ---
    k_gemm0<<<GEMM_GRID, 256>>>(X, W1, cs, hs);
    k_aggstats<<<agg_grid, 256>>>(hs, csr_start, indeg, csr_src, cd, y, stats);

    // --- layer 1 gemm + layer 0 readout (combined) ---
    k_gemm_ro<<<GEMM_GRID + GG, 256>>>(y, W2, cs, stats, gw, gb, gs, hs,
                                       gstart, out, 0);
    k_aggstats<<<agg_grid, 256>>>(hs, csr_start, indeg, csr_src, cd, y,
                                  stats + 2 * HID);

    // --- layer 2 gemm + layer 1 readout (combined) ---
    k_gemm_ro<<<GEMM_GRID + GG, 256>>>(y, W3, cs, stats + 2 * HID,
                                       gw + HID, gb + HID, gs + HID, hs,
                                       gstart, out, 1);
    k_aggstats<<<agg_grid, 256>>>(hs, csr_start, indeg, csr_src, cd, y,
                                  stats + 4 * HID);

    // --- final readout ---
    k_readout<<<GG, 256>>>(y, stats + 4 * HID, gw + 2 * HID, gb + 2 * HID,
                           gs + 2 * HID, gstart, out, 2);

    // --- trailing zero: restore state for next call ---
    k_setup_zero<<<256, 256>>>(deg, stats, total);
}

// round 17
// speedup vs baseline: 1.0289x; 1.0289x over previous
#include <cuda_runtime.h>
#include <cuda_fp16.h>
#include <math_constants.h>
#include <cstdint>

// Problem constants (fixed by the dataset)
#define NN   50000
#define EE   600000
#define GG   1000
#define HID  128
#define INF_ 64
#define EPS  1e-5f
#define SLOPE 0.01f

#define NB_SCAN ((NN + 255) / 256)   // 196
#define BUF_E 8                      // edges per TMA batch per warp
#define GEMM_GRID ((NN + 63) / 64)   // 782 (64-row blocks)

// ---------------------------------------------------------------------------
// Scratch (static __device__ arrays; zero-initialized at load; the trailing
// k_setup_zero restores zeros for the NEXT call -> identical state per call).
// ---------------------------------------------------------------------------
__device__ __align__(256) __half g_hs [NN * HID];  // (x@W)*cs fp16, 256B rows
__device__ float  g_y  [NN * HID];
__device__ float  g_cs [NN];
__device__ float  g_cd [NN];
__device__ int    g_deg[2 * NN];     // [0,N): outdeg, [N,2N): indeg
__device__ int    g_csr_start[NN];   // segment base per node (non-monotonic)
__device__ int    g_cursor[NN];
__device__ int    g_csr_src[EE];
__device__ int    g_total[1];        // atomic segment allocator
__device__ float  g_stats[3 * 2 * HID];
__device__ int    g_gstart[GG + 1];

__device__ __forceinline__ float leaky(float v) { return v > 0.f ? v : SLOPE * v; }

__device__ __forceinline__ void alpha_beta(const float* __restrict__ stats,
                                           const float* __restrict__ gw,
                                           const float* __restrict__ gb,
                                           const float* __restrict__ gs,
                                           int c, float& a, float& b) {
    float m   = stats[c] * (1.f / (float)NN);
    float ex2 = stats[HID + c] * (1.f / (float)NN);
    float s   = gs[c];
    float var = ex2 - m * m * (2.f * s - s * s);
    float inv = rsqrtf(var + EPS);
    a = inv * gw[c];
    b = gb[c] - s * m * a;
}

// packed f32x2 helpers
__device__ __forceinline__ unsigned long long pack2(float x, float y) {
    unsigned long long r;
    asm("mov.b64 %0, {%1, %2};" : "=l"(r) : "f"(x), "f"(y));
    return r;
}
__device__ __forceinline__ void unpack2(unsigned long long p, float& x, float& y) {
    asm("mov.b64 {%0, %1}, %2;" : "=f"(x), "=f"(y) : "l"(p));
}
__device__ __forceinline__ void fma2(unsigned long long& d, unsigned long long a,
                                     unsigned long long b) {
    asm("fma.rn.f32x2 %0, %1, %2, %0;" : "+l"(d) : "l"(a), "l"(b));
}

__device__ __forceinline__ uint32_t smem_u32(const void* p) {
    return (uint32_t)__cvta_generic_to_shared(p);
}
__device__ __forceinline__ void mbar_wait(uint32_t mbar, uint32_t parity) {
    asm volatile(
        "{\n\t.reg .pred P1;\n\t"
        "W_%=:\n\t"
        "mbarrier.try_wait.parity.acquire.cta.shared::cta.b64 P1, [%0], %1, 0x989680;\n\t"
        "@P1 bra.uni D_%=;\n\t"
        "bra.uni W_%=;\n\t"
        "D_%=:\n\t}"
        :: "r"(mbar), "r"(parity) : "memory");
}

// ---------------------------------------------------------------------------
// Trailing zero: restores deg + stats + total for the NEXT call.
// ---------------------------------------------------------------------------
__global__ void k_setup_zero(int* __restrict__ deg, float* __restrict__ stats,
                             int* __restrict__ total) {
    int i = blockIdx.x * blockDim.x + threadIdx.x;
    int stride = gridDim.x * blockDim.x;
    for (int j = i; j < 2 * NN; j += stride) deg[j] = 0;
    for (int j = i; j < 3 * 2 * HID; j += stride) stats[j] = 0.f;
    if (i == 0) total[0] = 0;
}

// ---------------------------------------------------------------------------
// Degrees: 4 edges/thread; deg[] arrives zeroed
// ---------------------------------------------------------------------------
__global__ void k_degrees(const int* __restrict__ src, const int* __restrict__ dst,
                          int* __restrict__ deg) {
    int base = (blockIdx.x * blockDim.x + threadIdx.x) * 4;
    if (base >= EE) return;
    int4 s4 = *(const int4*)&src[base];
    int4 d4 = *(const int4*)&dst[base];
    atomicAdd(&deg[s4.x], 1);
    atomicAdd(&deg[s4.y], 1);
    atomicAdd(&deg[s4.z], 1);
    atomicAdd(&deg[s4.w], 1);
    atomicAdd(&deg[NN + d4.x], 1);
    atomicAdd(&deg[NN + d4.y], 1);
    atomicAdd(&deg[NN + d4.z], 1);
    atomicAdd(&deg[NN + d4.w], 1);
}

// ---------------------------------------------------------------------------
// Fused post-degree setup: invdeg + gstart + CSR segment assignment
// ---------------------------------------------------------------------------
__global__ void k_misc(const int* __restrict__ deg, const int* __restrict__ gid,
                       float* __restrict__ cs, float* __restrict__ cd,
                       int* __restrict__ gstart, int* __restrict__ csr_start,
                       int* __restrict__ cursor, int* __restrict__ total) {
    __shared__ int sh[256];
    __shared__ int s_base;
    int t = threadIdx.x;
    int i = blockIdx.x * 256 + t;
    int v = 0;
    if (i < NN) {
        int od = deg[i], id = deg[NN + i];
        cs[i] = rsqrtf(fmaxf((float)od, 1.f));
        cd[i] = rsqrtf(fmaxf((float)id, 1.f));
        v = id;
        int g  = gid[i];
        int gp = (i == 0) ? -1 : gid[i - 1];
        for (int gg = gp + 1; gg <= g; gg++) gstart[gg] = i;
        if (i == NN - 1)
            for (int gg = g + 1; gg <= GG; gg++) gstart[gg] = NN;
    }
    sh[t] = v;
    __syncthreads();
    for (int o = 1; o < 256; o <<= 1) {
        int tv = (t >= o) ? sh[t - o] : 0;
        __syncthreads();
        sh[t] += tv;
        __syncthreads();
    }
    if (t == 255) s_base = atomicAdd(total, sh[255]);
    __syncthreads();
    if (i < NN) {
        int start = s_base + sh[t] - v;
        csr_start[i] = start;
        cursor[i] = start;
    }
}

// ---------------------------------------------------------------------------
// CSR fill: 4 edges per thread
// ---------------------------------------------------------------------------
__global__ void k_fill_csr(const int* __restrict__ src, const int* __restrict__ dst,
                           int* __restrict__ cursor, int* __restrict__ csr_src) {
    int base = (blockIdx.x * blockDim.x + threadIdx.x) * 4;
    if (base >= EE) return;
    int4 s4 = *(const int4*)&src[base];
    int4 d4 = *(const int4*)&dst[base];
    int p0 = atomicAdd(&cursor[d4.x], 1);
    int p1 = atomicAdd(&cursor[d4.y], 1);
    int p2 = atomicAdd(&cursor[d4.z], 1);
    int p3 = atomicAdd(&cursor[d4.w], 1);
    csr_src[p0] = s4.x;
    csr_src[p1] = s4.y;
    csr_src[p2] = s4.z;
    csr_src[p3] = s4.w;
}

// ---------------------------------------------------------------------------
// GEMM device body (packed f32x2): block = 64 rows x 128 cols, 8 warps,
// micro-tile 8 rows x 4 cols (4 packed row-pairs) -> ~32 acc regs, enabling
// 3 blocks/SM (24 warps) for latency hiding (round-16 ncu: occ 21%, issue 34%).
// ---------------------------------------------------------------------------
template <int K, bool NORM>
__device__ __forceinline__ void gemm_body(
    int blk, const float* __restrict__ X, const float* __restrict__ W,
    const float* __restrict__ cs, const float* __restrict__ s_a,
    const float* __restrict__ s_b, __half* __restrict__ out,
    float (*Ws)[HID], float (*Xs)[68]) {
    int tid = threadIdx.x;
    int tx = tid & 31, ty = tid >> 5;
    int row0 = blk * 64;
    int rb = ty * 8, cb = tx * 4;

    unsigned long long acc[4][4];
#pragma unroll
    for (int i = 0; i < 4; i++)
#pragma unroll
        for (int j = 0; j < 4; j++) acc[i][j] = 0ull;

    for (int k0 = 0; k0 < K; k0 += 32) {
        for (int i = tid; i < 32 * 32; i += 256) {
            int k = i >> 5, c = (i & 31) * 4;
            *(float4*)&Ws[k][c] = *(const float4*)&W[(k0 + k) * HID + c];
        }
        for (int i = tid; i < 64 * 8; i += 256) {
            int r = i >> 3, kq = (i & 7) * 4;
            int g = row0 + r;
            float4 v = make_float4(0.f, 0.f, 0.f, 0.f);
            if (g < NN) v = *(const float4*)&X[(size_t)g * K + k0 + kq];
            if (NORM) {
                float4 a = *(const float4*)&s_a[k0 + kq];
                float4 b = *(const float4*)&s_b[k0 + kq];
                v.x = leaky(v.x * a.x + b.x);
                v.y = leaky(v.y * a.y + b.y);
                v.z = leaky(v.z * a.z + b.z);
                v.w = leaky(v.w * a.w + b.w);
            }
            Xs[kq + 0][r] = v.x;
            Xs[kq + 1][r] = v.y;
            Xs[kq + 2][r] = v.z;
            Xs[kq + 3][r] = v.w;
        }
        __syncthreads();

#pragma unroll
        for (int k = 0; k < 32; k++) {
            ulonglong2 xa = *(const ulonglong2*)&Xs[k][rb];
            ulonglong2 xb = *(const ulonglong2*)&Xs[k][rb + 4];
            float4 w = *(const float4*)&Ws[k][cb];
            unsigned long long w0 = pack2(w.x, w.x);
            unsigned long long w1 = pack2(w.y, w.y);
            unsigned long long w2 = pack2(w.z, w.z);
            unsigned long long w3 = pack2(w.w, w.w);
            fma2(acc[0][0], xa.x, w0); fma2(acc[0][1], xa.x, w1);
            fma2(acc[0][2], xa.x, w2); fma2(acc[0][3], xa.x, w3);
            fma2(acc[1][0], xa.y, w0); fma2(acc[1][1], xa.y, w1);
            fma2(acc[1][2], xa.y, w2); fma2(acc[1][3], xa.y, w3);
            fma2(acc[2][0], xb.x, w0); fma2(acc[2][1], xb.x, w1);
            fma2(acc[2][2], xb.x, w2); fma2(acc[2][3], xb.x, w3);
            fma2(acc[3][0], xb.y, w0); fma2(acc[3][1], xb.y, w1);
            fma2(acc[3][2], xb.y, w2); fma2(acc[3][3], xb.y, w3);
        }
        __syncthreads();
    }

#pragma unroll
    for (int rp = 0; rp < 4; rp++) {
        float lo[4], hi[4];
#pragma unroll
        for (int c = 0; c < 4; c++) unpack2(acc[rp][c], lo[c], hi[c]);
        int g0 = row0 + rb + 2 * rp;
        int g1 = g0 + 1;
        if (g0 < NN) {
            float c0 = __ldg(&cs[g0]);
            __half2 p0 = __floats2half2_rn(lo[0] * c0, lo[1] * c0);
            __half2 p1 = __floats2half2_rn(lo[2] * c0, lo[3] * c0);
            uint2 u;
            u.x = *reinterpret_cast<uint32_t*>(&p0);
            u.y = *reinterpret_cast<uint32_t*>(&p1);
            *(uint2*)&out[(size_t)g0 * HID + cb] = u;
        }
        if (g1 < NN) {
            float c1 = __ldg(&cs[g1]);
            __half2 p0 = __floats2half2_rn(hi[0] * c1, hi[1] * c1);
            __half2 p1 = __floats2half2_rn(hi[2] * c1, hi[3] * c1);
            uint2 u;
            u.x = *reinterpret_cast<uint32_t*>(&p0);
            u.y = *reinterpret_cast<uint32_t*>(&p1);
            *(uint2*)&out[(size_t)g1 * HID + cb] = u;
        }
    }
}

// ---------------------------------------------------------------------------
// Readout device body: one graph, 256 threads = 128 channels x 2 phases.
// ---------------------------------------------------------------------------
__device__ __forceinline__ void readout_body(
    int g, const float* __restrict__ y, float a, float b,
    const int* __restrict__ gstart, float* __restrict__ out, int layer,
    float* s_r0, float* s_r1, float* s_r2) {
    int t = threadIdx.x;
    int c = t & 127, ph = t >> 7;
    int s0 = gstart[g], s1 = gstart[g + 1];
    float sum = 0.f, mx = -CUDART_INF_F, mn = CUDART_INF_F;
    for (int r = s0 + ph; r < s1; r += 2) {
        float v = leaky(__ldg(&y[(size_t)r * HID + c]) * a + b);
        sum += v;
        mx = fmaxf(mx, v);
        mn = fminf(mn, v);
    }
    s_r0[t] = sum; s_r1[t] = mx; s_r2[t] = mn;
    __syncthreads();
    if (ph == 0) {
        sum += s_r0[t + 128];
        mx = fmaxf(mx, s_r1[t + 128]);
        mn = fminf(mn, s_r2[t + 128]);
        int cnt = s1 - s0;
        float mean = sum / fmaxf((float)cnt, 1.f);
        if (cnt == 0) { mx = 0.f; mn = 0.f; }
        float* o = out + (size_t)g * (9 * HID) + layer * (3 * HID);
        o[c]           = leaky(mean);
        o[HID + c]     = leaky(mx);
        o[2 * HID + c] = leaky(mn);
    }
}

// ---------------------------------------------------------------------------
// Layer-0 GEMM (no norm). Launched at slot #4 -> profiled by ncu.
// ---------------------------------------------------------------------------
__global__ void __launch_bounds__(256, 3)
k_gemm0(const float* __restrict__ X, const float* __restrict__ W,
        const float* __restrict__ cs, __half* __restrict__ out) {
    __shared__ float Ws[32][HID];
    __shared__ float Xs[32][68];
    gemm_body<INF_, false>(blockIdx.x, X, W, cs, nullptr, nullptr, out, Ws, Xs);
}

// ---------------------------------------------------------------------------
// Combined: blocks [0,GEMM_GRID) gemm(L) w/ norm(L-1); [GEMM_GRID,+GG)
// readout(L-1). Both depend only on agg(L-1); disjoint memory.
// ---------------------------------------------------------------------------
__global__ void __launch_bounds__(256, 3)
k_gemm_ro(const float* __restrict__ y, const float* __restrict__ W,
          const float* __restrict__ cs,
          const float* __restrict__ stats, const float* __restrict__ gw,
          const float* __restrict__ gb, const float* __restrict__ gs,
          __half* __restrict__ hs, const int* __restrict__ gstart,
          float* __restrict__ out, int prev_layer) {
    __shared__ float Ws[32][HID];
    __shared__ float Xs[32][68];
    __shared__ float s_a[HID], s_b[HID];

    int bid = blockIdx.x;
    if (bid < GEMM_GRID) {
        if (threadIdx.x < HID) {
            float a, b;
            alpha_beta(stats, gw, gb, gs, threadIdx.x, a, b);
            s_a[threadIdx.x] = a;
            s_b[threadIdx.x] = b;
        }
        __syncthreads();
        gemm_body<HID, true>(bid, y, W, cs, s_a, s_b, hs, Ws, Xs);
    } else {
        float a, b;
        alpha_beta(stats, gw, gb, gs, threadIdx.x & 127, a, b);
        float* s_r0 = &Ws[0][0];
        float* s_r1 = &Ws[2][0];
        float* s_r2 = &Ws[4][0];
        readout_body(bid - GEMM_GRID, y, a, b, gstart, out, prev_layer,
                     s_r0, s_r1, s_r2);
    }
}

// ---------------------------------------------------------------------------
// Standalone readout (final layer)
// ---------------------------------------------------------------------------
__global__ void __launch_bounds__(256)
k_readout(const float* __restrict__ y, const float* __restrict__ stats,
          const float* __restrict__ gw, const float* __restrict__ gb,
          const float* __restrict__ gs, const int* __restrict__ gstart,
          float* __restrict__ out, int layer) {
    __shared__ float s_r0[256], s_r1[256], s_r2[256];
    float a, b;
    alpha_beta(stats, gw, gb, gs, threadIdx.x & 127, a, b);
    readout_body(blockIdx.x, y, a, b, gstart, out, layer, s_r0, s_r1, s_r2);
}

// ---------------------------------------------------------------------------
// TMA-bulk aggregation (round-11 proven). end = start + indeg[d].
// ---------------------------------------------------------------------------
__global__ void __launch_bounds__(256)
k_aggstats(const __half* __restrict__ hs, const int* __restrict__ csr_start,
           const int* __restrict__ indeg, const int* __restrict__ csr_src,
           const float* __restrict__ cd,
           float* __restrict__ y, float* __restrict__ stats) {
    __shared__ __align__(16) char buf[8][BUF_E * 256];   // 16 KB
    __shared__ __align__(8) uint64_t mbar[8];
    __shared__ float s_sum[8][HID];
    __shared__ float s_sq [8][HID];

    int warp = threadIdx.x >> 5, lane = threadIdx.x & 31;
    int lg = lane >> 4, li = lane & 15;
    int d = blockIdx.x * 8 + warp;
    uint32_t mb = smem_u32(&mbar[warp]);

    if (lane == 0)
        asm volatile("mbarrier.init.shared.b64 [%0], 1;" :: "r"(mb) : "memory");
    __syncwarp();

    float2 acc[4];
#pragma unroll
    for (int j = 0; j < 4; j++) acc[j] = make_float2(0.f, 0.f);

    if (d < NN) {
        int start = __ldg(&csr_start[d]);
        int end   = start + __ldg(&indeg[d]);
        uint32_t parity = 0;
        for (int i = start; i < end; i += BUF_E) {
            int cnt = min(BUF_E, end - i);
            if (lane == 0)
                asm volatile(
                    "mbarrier.arrive.expect_tx.shared.b64 _, [%0], %1;"
                    :: "r"(mb), "r"((uint32_t)(cnt * 256)) : "memory");
            __syncwarp();
            if (lane < cnt) {
                int s = __ldg(&csr_src[i + lane]);
                uint32_t dstp = smem_u32(&buf[warp][lane * 256]);
                const void* gsrc = hs + (size_t)s * HID;
                asm volatile(
                    "cp.async.bulk.shared::cluster.global.mbarrier::complete_tx::bytes "
                    "[%0], [%1], %2, [%3];"
                    :: "r"(dstp), "l"(gsrc), "r"(256u), "r"(mb) : "memory");
            }
            mbar_wait(mb, parity);
            parity ^= 1u;
            for (int j = lg; j < cnt; j += 2) {
                uint4 u = *(const uint4*)&buf[warp][j * 256 + li * 16];
                float2 f;
                f = __half22float2(*reinterpret_cast<__half2*>(&u.x));
                acc[0].x += f.x; acc[0].y += f.y;
                f = __half22float2(*reinterpret_cast<__half2*>(&u.y));
                acc[1].x += f.x; acc[1].y += f.y;
                f = __half22float2(*reinterpret_cast<__half2*>(&u.z));
                acc[2].x += f.x; acc[2].y += f.y;
                f = __half22float2(*reinterpret_cast<__half2*>(&u.w));
                acc[3].x += f.x; acc[3].y += f.y;
            }
            __syncwarp();
        }
#pragma unroll
        for (int j = 0; j < 4; j++) {
            acc[j].x += __shfl_xor_sync(0xffffffffu, acc[j].x, 16);
            acc[j].y += __shfl_xor_sync(0xffffffffu, acc[j].y, 16);
        }
        float c = __ldg(&cd[d]);
#pragma unroll
        for (int j = 0; j < 4; j++) { acc[j].x *= c; acc[j].y *= c; }
        if (lg == 0) {
            float4 o0 = make_float4(acc[0].x, acc[0].y, acc[1].x, acc[1].y);
            float4 o1 = make_float4(acc[2].x, acc[2].y, acc[3].x, acc[3].y);
            *(float4*)(y + (size_t)d * HID + li * 8)     = o0;
            *(float4*)(y + (size_t)d * HID + li * 8 + 4) = o1;
        }
    }

    if (lg == 0) {
#pragma unroll
        for (int j = 0; j < 4; j++) {
            int c0 = li * 8 + 2 * j;
            float vx = (d < NN) ? acc[j].x : 0.f;
            float vy = (d < NN) ? acc[j].y : 0.f;
            s_sum[warp][c0]     = vx;
            s_sum[warp][c0 + 1] = vy;
            s_sq [warp][c0]     = vx * vx;
            s_sq [warp][c0 + 1] = vy * vy;
        }
    }
    __syncthreads();

    int t = threadIdx.x;
    if (t < HID) {
        float s = 0.f;
#pragma unroll
        for (int w = 0; w < 8; w++) s += s_sum[w][t];
        atomicAdd(&stats[t], s);
    } else {
        int c = t - HID;
        float s = 0.f;
#pragma unroll
        for (int w = 0; w < 8; w++) s += s_sq[w][c];
        atomicAdd(&stats[HID + c], s);
    }
}

// ---------------------------------------------------------------------------
// Launch: single stream, 11 launches. gemm0 at slot #4 (profiled);
// trailing k_setup_zero restores zeroed state for the next call.
// ---------------------------------------------------------------------------
extern "C" void kernel_launch(void* const* d_in, const int* in_sizes, int n_in,
                              void* d_out, int out_size) {
    const float* X   = (const float*)d_in[0];
    const float* W1  = (const float*)d_in[1];
    const float* W2  = (const float*)d_in[2];
    const float* W3  = (const float*)d_in[3];
    const float* gw  = (const float*)d_in[4];
    const float* gb  = (const float*)d_in[5];
    const float* gs  = (const float*)d_in[6];
    const int*   src = (const int*)d_in[7];
    const int*   dst = (const int*)d_in[8];
    const int*   gid = (const int*)d_in[9];
    float* out = (float*)d_out;

    __half* hs;
    float *y, *cs, *cd, *stats;
    int *deg, *gstart, *csr_start, *cursor, *csr_src, *total;
    cudaGetSymbolAddress((void**)&hs,        g_hs);
    cudaGetSymbolAddress((void**)&y,         g_y);
    cudaGetSymbolAddress((void**)&cs,        g_cs);
    cudaGetSymbolAddress((void**)&cd,        g_cd);
    cudaGetSymbolAddress((void**)&stats,     g_stats);
    cudaGetSymbolAddress((void**)&deg,       g_deg);
    cudaGetSymbolAddress((void**)&gstart,    g_gstart);
    cudaGetSymbolAddress((void**)&csr_start, g_csr_start);
    cudaGetSymbolAddress((void**)&cursor,    g_cursor);
    cudaGetSymbolAddress((void**)&csr_src,   g_csr_src);
    cudaGetSymbolAddress((void**)&total,     g_total);

    const int agg_grid   = (NN + 7) / 8;
    const int edge4_grid = (EE / 4 + 255) / 256;
    int* indeg = deg + NN;

    // --- setup: 3 launches (deg/stats/total arrive zeroed) ---
    k_degrees<<<edge4_grid, 256>>>(src, dst, deg);
    k_misc<<<NB_SCAN, 256>>>(deg, gid, cs, cd, gstart, csr_start, cursor, total);
    k_fill_csr<<<edge4_grid, 256>>>(src, dst, cursor, csr_src);

    // --- layer 0 (gemm0 at launch slot #4 -> gets profiled) ---
    k_gemm0<<<GEMM_GRID, 256>>>(X, W1, cs, hs);
    k_aggstats<<<agg_grid, 256>>>(hs, csr_start, indeg, csr_src, cd, y, stats);

    // --- layer 1 gemm + layer 0 readout (combined) ---
    k_gemm_ro<<<GEMM_GRID + GG, 256>>>(y, W2, cs, stats, gw, gb, gs, hs,
                                       gstart, out, 0);
    k_aggstats<<<agg_grid, 256>>>(hs, csr_start, indeg, csr_src, cd, y,
                                  stats + 2 * HID);

    // --- layer 2 gemm + layer 1 readout (combined) ---
    k_gemm_ro<<<GEMM_GRID + GG, 256>>>(y, W3, cs, stats + 2 * HID,
                                       gw + HID, gb + HID, gs + HID, hs,
                                       gstart, out, 1);
    k_aggstats<<<agg_grid, 256>>>(hs, csr_start, indeg, csr_src, cd, y,
                                  stats + 4 * HID);

    // --- final readout ---
    k_readout<<<GG, 256>>>(y, stats + 4 * HID, gw + 2 * HID, gb + 2 * HID,
                           gs + 2 * HID, gstart, out, 2);

    // --- trailing zero: restore state for next call ---
    k_setup_zero<<<256, 256>>>(deg, stats, total);
}